// round 13
// baseline (speedup 1.0000x reference)
#include <cuda_runtime.h>
#include <cstdint>

#define OUT_F 28672
#define IN_F  8192
#define ROW_BYTES 16384            // int32-widened qweight row: 4096 * 4 B
#define NW  4                      // warps per block
#define RPW 4                      // rows per warp
#define RPB (NW * RPW)             // 16 rows per block
#define CHUNK_B 1024               // bytes per row per chunk
#define NCHUNK (ROW_BYTES / CHUNK_B)   // 16
#define WSTAGE_B (RPW * CHUNK_B)       // 4 KB per warp-stage

// qweight is int32 (harness-widened uint8): each element is a byte value
// 0..255 = two 4-bit codes (lo nibble -> even column, hi nibble -> odd).
//
// Endpoint of the convoy-domain lever (R10 8w:71.6% -> R11 4w:79.0% ->
// R12 2w:77.1%): barrier domain = ONE warp. Each warp owns 4 rows and a
// private double-buffered 4 KB ring + its own full-mbarrier. Lane 0 issues
// the 4x1KB TMA copies; refill of a stage is issued right after the warp
// consumed it (program order makes this safe: the TMA issue follows the FMAs,
// which issue only after all LDS results landed). No __syncthreads, no empty
// barriers, no cross-warp coupling in the mainloop.

__device__ __forceinline__ uint32_t smem_u32(const void* p) {
    return (uint32_t)__cvta_generic_to_shared(p);
}
__device__ __forceinline__ void mbar_init(uint32_t mbar, uint32_t count) {
    asm volatile("mbarrier.init.shared.b64 [%0], %1;" :: "r"(mbar), "r"(count) : "memory");
}
__device__ __forceinline__ void mbar_expect_tx(uint32_t mbar, uint32_t bytes) {
    asm volatile("mbarrier.arrive.expect_tx.shared.b64 _, [%0], %1;"
                 :: "r"(mbar), "r"(bytes) : "memory");
}
__device__ __forceinline__ void bulk_g2s(uint32_t dst, const void* src,
                                         uint32_t bytes, uint32_t mbar) {
    asm volatile(
        "cp.async.bulk.shared::cluster.global.mbarrier::complete_tx::bytes "
        "[%0], [%1], %2, [%3];"
        :: "r"(dst), "l"(src), "r"(bytes), "r"(mbar) : "memory");
}
__device__ __forceinline__ void mbar_wait(uint32_t mbar, uint32_t parity) {
    uint32_t done;
    asm volatile(
        "{\n\t.reg .pred p;\n\t"
        "mbarrier.try_wait.parity.acquire.cta.shared::cta.b64 p, [%1], %2;\n\t"
        "selp.b32 %0, 1, 0, p;\n\t}"
        : "=r"(done) : "r"(mbar), "r"(parity) : "memory");
    if (!done) {
        asm volatile(
            "{\n\t.reg .pred P1;\n\t"
            "WL_%=:\n\t"
            "mbarrier.try_wait.parity.acquire.cta.shared::cta.b64 P1, [%0], %1, 0x989680;\n\t"
            "@P1 bra.uni WD_%=;\n\t"
            "bra.uni WL_%=;\n\t"
            "WD_%=:\n\t}"
            :: "r"(mbar), "r"(parity) : "memory");
    }
}

__global__ __launch_bounds__(128, 6)
void q3_matvec_kernel(const float* __restrict__ x,
                      const int* __restrict__ qw,
                      const float* __restrict__ kv,
                      const float* __restrict__ bias,
                      float* __restrict__ y)
{
    // Per-warp private rings: [warp][stage][4 rows x 1 KB]
    __shared__ alignas(128) uint8_t s_buf[NW][2][WSTAGE_B];   // 32 KB
    __shared__ float s_lut[RPB * 16];                         // 16 row-LUTs
    __shared__ alignas(8) uint64_t s_full[NW][2];

    const int t = threadIdx.x;
    const int w = t >> 5;
    const int l = t & 31;
    const int rbase = blockIdx.x * RPB;
    const int wrow = rbase + (w << 2);      // this warp's 4 rows

    // Stage 256 LUT floats (2 per thread).
    s_lut[t]       = kv[rbase * 16 + t];
    s_lut[t + 128] = kv[rbase * 16 + t + 128];

    const uint32_t fb0 = smem_u32(&s_full[w][0]);
    const uint32_t fb1 = smem_u32(&s_full[w][1]);
    const uint32_t bu0 = smem_u32(&s_buf[w][0][0]);
    const uint32_t bu1 = smem_u32(&s_buf[w][1][0]);

    if (l == 0) { mbar_init(fb0, 1); mbar_init(fb1, 1); }
    // One sync so LUT + all warps' barriers are initialized before use.
    __syncthreads();

    const char* gq = (const char*)qw + (size_t)wrow * ROW_BYTES;

    // Prologue: this warp fills its own two stages (chunks 0 and 1).
    if (l == 0) {
        mbar_expect_tx(fb0, WSTAGE_B);
        #pragma unroll
        for (int r = 0; r < RPW; r++)
            bulk_g2s(bu0 + r * CHUNK_B, gq + (size_t)r * ROW_BYTES, CHUNK_B, fb0);
        mbar_expect_tx(fb1, WSTAGE_B);
        #pragma unroll
        for (int r = 0; r < RPW; r++)
            bulk_g2s(bu1 + r * CHUNK_B, gq + (size_t)r * ROW_BYTES + CHUNK_B, CHUNK_B, fb1);
    }

    const float* lut0 = s_lut + (w << 2) * 16;
    const float4* xp = reinterpret_cast<const float4*>(x);

    float a00 = 0.f, a01 = 0.f;
    float a10 = 0.f, a11 = 0.f;
    float a20 = 0.f, a21 = 0.f;
    float a30 = 0.f, a31 = 0.f;

    #pragma unroll 1
    for (int c = 0; c < NCHUNK; c++) {
        const int st = c & 1;
        const uint32_t fb = st ? fb1 : fb0;
        const uint32_t bu = st ? bu1 : bu0;
        mbar_wait(fb, (c >> 1) & 1);

        const uint8_t* wbuf = (st ? &s_buf[w][1][0] : &s_buf[w][0][0]);

        // Two 512 B half-chunks per row; x window per half from L1.
        #pragma unroll
        for (int h = 0; h < 2; h++) {
            const float4 xa = xp[(c << 7) + (h << 6) + (l << 1)];
            const float4 xb = xp[(c << 7) + (h << 6) + (l << 1) + 1];
            const uint8_t* buf = wbuf + (h << 9) + (l << 4);

            const uint4 q0 = *reinterpret_cast<const uint4*>(buf);
            const uint4 q1 = *reinterpret_cast<const uint4*>(buf + CHUNK_B);
            const uint4 q2 = *reinterpret_cast<const uint4*>(buf + 2 * CHUNK_B);
            const uint4 q3 = *reinterpret_cast<const uint4*>(buf + 3 * CHUNK_B);

            // v <= 255 so (v >> 4) is already a clean code (no mask).
            #define DO_ROW(Q, LUT, A0, A1)                        \
                A0 = fmaf((LUT)[(Q).x & 15u], xa.x, A0);          \
                A1 = fmaf((LUT)[(Q).x >> 4],  xa.y, A1);          \
                A0 = fmaf((LUT)[(Q).y & 15u], xa.z, A0);          \
                A1 = fmaf((LUT)[(Q).y >> 4],  xa.w, A1);          \
                A0 = fmaf((LUT)[(Q).z & 15u], xb.x, A0);          \
                A1 = fmaf((LUT)[(Q).z >> 4],  xb.y, A1);          \
                A0 = fmaf((LUT)[(Q).w & 15u], xb.z, A0);          \
                A1 = fmaf((LUT)[(Q).w >> 4],  xb.w, A1);

            DO_ROW(q0, lut0,      a00, a01)
            DO_ROW(q1, lut0 + 16, a10, a11)
            DO_ROW(q2, lut0 + 32, a20, a21)
            DO_ROW(q3, lut0 + 48, a30, a31)
            #undef DO_ROW
        }

        // Self-paced refill: this stage is consumed (all LDS results landed
        // before the FMAs above could issue) -> reload it with chunk c+2.
        if (c + 2 < NCHUNK && l == 0) {
            mbar_expect_tx(fb, WSTAGE_B);
            const char* src = gq + (size_t)(c + 2) * CHUNK_B;
            #pragma unroll
            for (int r = 0; r < RPW; r++)
                bulk_g2s(bu + r * CHUNK_B, src + (size_t)r * ROW_BYTES, CHUNK_B, fb);
        }
    }

    // Four reductions per warp, once.
    float r0 = a00 + a01;
    float r1 = a10 + a11;
    float r2 = a20 + a21;
    float r3 = a30 + a31;
    #pragma unroll
    for (int s = 16; s > 0; s >>= 1) {
        r0 += __shfl_xor_sync(0xffffffffu, r0, s);
        r1 += __shfl_xor_sync(0xffffffffu, r1, s);
        r2 += __shfl_xor_sync(0xffffffffu, r2, s);
        r3 += __shfl_xor_sync(0xffffffffu, r3, s);
    }
    if (l == 0) {
        y[wrow + 0] = r0 + bias[wrow + 0];
        y[wrow + 1] = r1 + bias[wrow + 1];
        y[wrow + 2] = r2 + bias[wrow + 2];
        y[wrow + 3] = r3 + bias[wrow + 3];
    }
}

extern "C" void kernel_launch(void* const* d_in, const int* in_sizes, int n_in,
                              void* d_out, int out_size)
{
    const float* x    = (const float*)d_in[0];
    const int*   qw   = (const int*)d_in[1];
    const float* kv   = (const float*)d_in[2];
    const float* bias = (const float*)d_in[3];
    float*       y    = (float*)d_out;

    dim3 grid(OUT_F / RPB);   // 1792 blocks of 4 warps (4 rows per warp)
    dim3 block(128);
    q3_matvec_kernel<<<grid, block>>>(x, qw, kv, bias, y);
}